// round 12
// baseline (speedup 1.0000x reference)
#include <cuda_runtime.h>
#include <cuda_bf16.h>
#include <math.h>
#include <stdint.h>

#define B_   8
#define T_   1024
#define D_   640
#define H_   10
#define HD   64
#define MTOT (B_*T_)      // 8192
#define DW   (D_/2)       // 320 u32 per row (packed bf16x2)
#define WN   (640*320)    // u32 per weight plane
// log2-domain mask constants:  x * log2(e)
#define QSCALE   0.18033688011112042f   // 0.125 * log2(e)
#define MASK2    (-14426.950408889634f) // -10000 * log2(e)
#define NEG_BIG2 (-6.1963290e9f)        // (-2^32+1) * log2(e)

// pre-split inputs (written by split_inputs)
__device__ uint32_t g_Xh[MTOT * DW];
__device__ uint32_t g_Xl[MTOT * DW];
__device__ uint32_t g_Wh[3 * WN];
__device__ uint32_t g_Wl[3 * WN];
// Q/K/V packed bf16x2 hi/lo planes (Q pre-scaled by QSCALE)
__device__ uint32_t g_Qh[MTOT * DW];
__device__ uint32_t g_Ql[MTOT * DW];
__device__ uint32_t g_Kh[MTOT * DW];
__device__ uint32_t g_Kl[MTOT * DW];
__device__ uint32_t g_Vh[MTOT * DW];
__device__ uint32_t g_Vl[MTOT * DW];
// precomputed masks: km bit per (hb, t); qf = q-sign-mask * row-mask
__device__ uint32_t g_kmbits[H_ * B_ * (T_ / 32)];
__device__ float    g_qf[H_ * B_ * T_];

// ===========================================================================
__device__ __forceinline__ uint32_t smem_u32(const void* p) {
    uint32_t a;
    asm("{ .reg .u64 t; cvta.to.shared.u64 t, %1; cvt.u32.u64 %0, t; }"
        : "=r"(a) : "l"(p));
    return a;
}
__device__ __forceinline__ void ldsm_x4(uint32_t* r, uint32_t addr) {
    asm volatile("ldmatrix.sync.aligned.m8n8.x4.shared.b16 {%0,%1,%2,%3}, [%4];"
        : "=r"(r[0]), "=r"(r[1]), "=r"(r[2]), "=r"(r[3]) : "r"(addr));
}
__device__ __forceinline__ void ldsm_x4_t(uint32_t* r, uint32_t addr) {
    asm volatile("ldmatrix.sync.aligned.m8n8.x4.trans.shared.b16 {%0,%1,%2,%3}, [%4];"
        : "=r"(r[0]), "=r"(r[1]), "=r"(r[2]), "=r"(r[3]) : "r"(addr));
}
__device__ __forceinline__ void mma16816(float* c, const uint32_t* a,
                                         uint32_t b0, uint32_t b1) {
    asm volatile(
        "mma.sync.aligned.m16n8k16.row.col.f32.bf16.bf16.f32 "
        "{%0,%1,%2,%3}, {%4,%5,%6,%7}, {%8,%9}, {%0,%1,%2,%3};"
        : "+f"(c[0]), "+f"(c[1]), "+f"(c[2]), "+f"(c[3])
        : "r"(a[0]), "r"(a[1]), "r"(a[2]), "r"(a[3]), "r"(b0), "r"(b1));
}
__device__ __forceinline__ float exp2f_fast(float x) {
    float r; asm("ex2.approx.f32 %0, %1;" : "=f"(r) : "f"(x)); return r;
}
// split pair (a,b) -> bf16 hi/lo packed bf16x2 (a low half)
__device__ __forceinline__ void bf16_split2(float a, float b,
                                            uint32_t& hi, uint32_t& lo) {
    asm("cvt.rn.bf16x2.f32 %0, %1, %2;" : "=r"(hi) : "f"(b), "f"(a));
    float ar = a - __uint_as_float(hi << 16);
    float br = b - __uint_as_float(hi & 0xFFFF0000u);
    asm("cvt.rn.bf16x2.f32 %0, %1, %2;" : "=r"(lo) : "f"(br), "f"(ar));
}
__device__ __forceinline__ void cp16(uint32_t dst, const void* src) {
    asm volatile("cp.async.cg.shared.global [%0], [%1], 16;"
        :: "r"(dst), "l"(src));
}
#define CP_COMMIT() asm volatile("cp.async.commit_group;" ::: "memory")
#define CP_WAIT(n)  asm volatile("cp.async.wait_group %0;" :: "n"(n) : "memory")

// ===========================================================================
// split_inputs: x and Wq/Wk/Wv fp32 -> packed bf16x2 hi/lo planes.
// ===========================================================================
__global__ void __launch_bounds__(256) split_inputs(
        const float* __restrict__ x,  const float* __restrict__ Wq,
        const float* __restrict__ Wk, const float* __restrict__ Wv)
{
    const int NX = MTOT * DW;
    const int NTOT = NX + 3 * WN;
    for (int i = blockIdx.x * 256 + threadIdx.x; i < NTOT;
         i += gridDim.x * 256) {
        if (i < NX) {
            float2 v = ((const float2*)x)[i];
            bf16_split2(v.x, v.y, g_Xh[i], g_Xl[i]);
        } else {
            int j = i - NX;
            int w = j / WN, r = j - w * WN;
            const float2* src = (const float2*)(w == 0 ? Wq : w == 1 ? Wk : Wv);
            float2 v = src[r];
            bf16_split2(v.x, v.y, g_Wh[j], g_Wl[j]);
        }
    }
}

// ===========================================================================
// mask_kernel: per (h,b,t) key-sign bit (ballot -> g_kmbits) and combined
// query factor g_qf = sign(sum|Q_h|) * mask[b][t].  grid 320 x 256 exactly.
// ===========================================================================
__global__ void __launch_bounds__(256) mask_kernel(const int* __restrict__ mask)
{
    const int idx = blockIdx.x * 256 + threadIdx.x;   // 0..81919
    const int hb = idx >> 10;           // h*8+b? -> hb = h<<3 | b (attn layout)
    const int t  = idx & 1023;
    const int h  = hb >> 3;
    const int b  = hb & 7;
    const size_t base = (size_t)(b * T_ + t) * DW + h * 32;

    uint32_t ok = 0, oq = 0;
    #pragma unroll
    for (int i = 0; i < 8; i++) {
        uint4 kh = *(const uint4*)(g_Kh + base + i * 4);
        uint4 kl = *(const uint4*)(g_Kl + base + i * 4);
        ok |= (kh.x | kh.y | kh.z | kh.w | kl.x | kl.y | kl.z | kl.w);
        uint4 qh = *(const uint4*)(g_Qh + base + i * 4);
        uint4 ql = *(const uint4*)(g_Ql + base + i * 4);
        oq |= (qh.x | qh.y | qh.z | qh.w | ql.x | ql.y | ql.z | ql.w);
    }
    ok &= 0x7FFF7FFFu;
    oq &= 0x7FFF7FFFu;

    uint32_t bits = __ballot_sync(0xffffffffu, ok != 0);
    if ((threadIdx.x & 31) == 0)
        g_kmbits[hb * 32 + (t >> 5)] = bits;
    g_qf[idx] = (oq != 0 ? 1.0f : 0.0f) * (float)mask[b * T_ + t];
}

// ===========================================================================
// Projection: double-buffered cp.async GEMM on pre-split bf16 planes.
// Q output (z==0) is pre-scaled by QSCALE (log2-domain softmax downstream).
// ===========================================================================
#define PS_AHI 0
#define PS_ALO 18432
#define PS_BHI 36864
#define PS_BLO 46080
#define PJ_STAGE 55296
#define PJ_SMEM  (2 * PJ_STAGE)   // 110592

__global__ void __launch_bounds__(256, 2) proj_tc_kernel()
{
    const int z = blockIdx.z;
    uint32_t* outh = (z == 0) ? g_Qh : (z == 1) ? g_Kh : g_Vh;
    uint32_t* outl = (z == 0) ? g_Ql : (z == 1) ? g_Kl : g_Vl;
    const uint32_t* wh = g_Wh + z * WN;
    const uint32_t* wl = g_Wl + z * WN;
    const float sc = (z == 0) ? QSCALE : 1.0f;

    extern __shared__ char smem[];
    const uint32_t sb = smem_u32(smem);

    const int tid  = threadIdx.x;
    const int lane = tid & 31;
    const int wid  = tid >> 5;
    const int wm   = (wid & 3) * 32;
    const int wn   = (wid >> 2) * 32;
    const int row0 = blockIdx.y * 128;
    const int col0 = blockIdx.x * 64;
    const int colw = col0 >> 1;

    auto load_chunk = [&](int s, int c) {
        const uint32_t base = sb + s * PJ_STAGE;
        const int kw = c * 32;
        #pragma unroll
        for (int i = 0; i < 8; i++) {
            const int plane = i >> 2;
            int rem = (tid + i * 256) & 1023;
            int r = rem >> 3, seg = rem & 7;
            const uint32_t* src = (plane ? g_Xl : g_Xh)
                                  + (size_t)(row0 + r) * DW + kw + seg * 4;
            cp16(base + (plane ? PS_ALO : PS_AHI) + r * 144 + seg * 16, src);
        }
        #pragma unroll
        for (int i = 0; i < 4; i++) {
            const int plane = i >> 1;
            int rem = (tid + i * 256) & 511;
            int kk = rem >> 3, seg = rem & 7;
            const uint32_t* src = (plane ? wl : wh)
                                  + (size_t)(c * 64 + kk) * 320 + colw + seg * 4;
            cp16(base + (plane ? PS_BLO : PS_BHI) + kk * 144 + seg * 16, src);
        }
        CP_COMMIT();
    };

    float acc[2][4][4] = {};
    load_chunk(0, 0);

    for (int c = 0; c < 10; c++) {
        if (c < 9) { load_chunk((c + 1) & 1, c + 1); CP_WAIT(1); }
        else       { CP_WAIT(0); }
        __syncthreads();

        const uint32_t base = sb + (c & 1) * PJ_STAGE;
        #pragma unroll
        for (int ks = 0; ks < 4; ks++) {
            const int k = ks * 16;
            uint32_t ah[2][4], al[2][4];
            #pragma unroll
            for (int mi = 0; mi < 2; mi++) {
                uint32_t off = (uint32_t)((wm + mi * 16 + (lane & 15)) * 72
                                          + k + (lane >> 4) * 8) * 2;
                ldsm_x4(ah[mi], base + PS_AHI + off);
                ldsm_x4(al[mi], base + PS_ALO + off);
            }
            uint32_t bh[2][4], bl[2][4];
            #pragma unroll
            for (int nj = 0; nj < 2; nj++) {
                uint32_t off = (uint32_t)((k + (lane & 15)) * 72
                                          + wn + nj * 16 + (lane >> 4) * 8) * 2;
                ldsm_x4_t(bh[nj], base + PS_BHI + off);
                ldsm_x4_t(bl[nj], base + PS_BLO + off);
            }
            #pragma unroll
            for (int mi = 0; mi < 2; mi++)
                #pragma unroll
                for (int ni = 0; ni < 4; ni++) {
                    int nj = ni >> 1, hf = (ni & 1) * 2;
                    mma16816(acc[mi][ni], ah[mi], bh[nj][hf], bh[nj][hf + 1]);
                    mma16816(acc[mi][ni], ah[mi], bl[nj][hf], bl[nj][hf + 1]);
                    mma16816(acc[mi][ni], al[mi], bh[nj][hf], bh[nj][hf + 1]);
                }
        }
        __syncthreads();
    }

    const int gid = lane >> 2, t2 = lane & 3;
    #pragma unroll
    for (int mi = 0; mi < 2; mi++) {
        #pragma unroll
        for (int ni = 0; ni < 4; ni++) {
            int r0r = row0 + wm + mi * 16 + gid;
            int cc  = col0 + wn + ni * 8 + t2 * 2;
            uint32_t h0, l0, h1, l1;
            bf16_split2(acc[mi][ni][0] * sc, acc[mi][ni][1] * sc, h0, l0);
            bf16_split2(acc[mi][ni][2] * sc, acc[mi][ni][3] * sc, h1, l1);
            size_t i0 = (size_t)r0r * DW + (cc >> 1);
            size_t i1 = (size_t)(r0r + 8) * DW + (cc >> 1);
            outh[i0] = h0; outl[i0] = l0;
            outh[i1] = h1; outl[i1] = l1;
        }
    }
}

// ===========================================================================
// Tensor-core flash attention.  CTA = (64-q-tile, head, batch), 4 warps.
// Q frags in registers; K double-buffered (prefetch hides gmem latency);
// V single-buffered (load overlaps QK); precomputed km bits / q factor.
// ===========================================================================
#define TS 72
#define AT_QHI 0
#define AT_QLO 9216
#define AT_K0  18432          // 2 stages x (KHI 9216 + KLO 9216)
#define AT_V   55296          // VHI + VLO
#define ATTN3_SMEM 73728

__global__ void __launch_bounds__(128, 3) attn_tc_kernel(float* __restrict__ out)
{
    const int q0 = blockIdx.x * 64;
    const int qt = blockIdx.x;
    const int hb = blockIdx.y;
    const int b  = hb & 7;
    const int h  = hb >> 3;

    extern __shared__ char sm[];
    const uint32_t sb = smem_u32(sm);

    const int tid  = threadIdx.x;
    const int lane = tid & 31;
    const int w    = tid >> 5;

    const size_t kvrow = (size_t)(b * T_) * DW + h * 32;

    // ---- Q tile
    {
        const uint32_t* qh = g_Qh + (size_t)(b * T_ + q0) * DW + h * 32;
        const uint32_t* ql = g_Ql + (size_t)(b * T_ + q0) * DW + h * 32;
        #pragma unroll
        for (int i = 0; i < 8; i++) {
            const int plane = i >> 2;
            int rem = (tid + i * 128) & 511;
            int r = rem >> 3, seg = rem & 7;
            cp16(sb + (plane ? AT_QLO : AT_QHI) + r * 144 + seg * 16,
                 (plane ? ql : qh) + (size_t)r * DW + seg * 4);
        }
        CP_COMMIT(); CP_WAIT(0);
    }
    __syncthreads();

    uint32_t qah[4][4], qal[4][4];
    #pragma unroll
    for (int ks = 0; ks < 4; ks++) {
        uint32_t aoff = (uint32_t)((16 * w + (lane & 15)) * TS
                                   + ks * 16 + (lane >> 4) * 8) * 2;
        ldsm_x4(qah[ks], sb + AT_QHI + aoff);
        ldsm_x4(qal[ks], sb + AT_QLO + aoff);
    }

    const int nkt = (q0 == 0) ? (T_ / 64) : (qt + 1);

    auto commitK = [&](int stg, int kt2) {
        const size_t gbase = kvrow + (size_t)(kt2 * 64) * DW;
        const uint32_t* kh = g_Kh + gbase;
        const uint32_t* kl = g_Kl + gbase;
        const uint32_t kbase = sb + AT_K0 + stg * 18432;
        #pragma unroll
        for (int i = 0; i < 8; i++) {
            const int plane = i >> 2;
            int rem = (tid + i * 128) & 511;
            int r = rem >> 3, seg = rem & 7;
            cp16(kbase + plane * 9216 + r * 144 + seg * 16,
                 (plane ? kl : kh) + (size_t)r * DW + seg * 4);
        }
        CP_COMMIT();
    };
    auto commitV = [&](int kt2) {
        const size_t gbase = kvrow + (size_t)(kt2 * 64) * DW;
        const uint32_t* vh = g_Vh + gbase;
        const uint32_t* vl = g_Vl + gbase;
        #pragma unroll
        for (int i = 0; i < 8; i++) {
            const int plane = i >> 2;
            int rem = (tid + i * 128) & 511;
            int r = rem >> 3, seg = rem & 7;
            cp16(sb + AT_V + plane * 9216 + r * 144 + seg * 16,
                 (plane ? vl : vh) + (size_t)r * DW + seg * 4);
        }
        CP_COMMIT();
    };

    commitK(0, 0);
    commitV(0);

    float m0 = -INFINITY, m1 = -INFINITY, l0 = 0.0f, l1 = 0.0f;
    float O[8][4] = {};

    for (int kt = 0; kt < nkt; kt++) {
        const int k0 = kt * 64;
        const bool fullmask = kt > qt;       // only q-tile 0
        const bool diag = (kt == qt);
        const uint32_t kvb = sb + AT_K0 + (kt & 1) * 18432;

        CP_WAIT(0);                 // K_kt resident (kt=0: V0 too)
        __syncthreads();            // all prior readers done

        if (kt > 0) commitV(kt);                       // V buf free now
        const bool havePref = (kt + 1 < nkt);
        if (havePref) commitK((kt + 1) & 1, kt + 1);   // other stage free

        // km bits for this tile (uniform load, L1-broadcast)
        const uint32_t kb0 = g_kmbits[hb * 32 + (k0 >> 5)];
        const uint32_t kb1 = g_kmbits[hb * 32 + (k0 >> 5) + 1];
        const bool allkm = (kb0 & kb1) == 0xFFFFFFFFu;

        // ---- S = Q K^T (3-term bf16 split); log2-domain scores
        float s[8][4] = {};
        #pragma unroll
        for (int ks = 0; ks < 4; ks++) {
            #pragma unroll
            for (int kg = 0; kg < 4; kg++) {
                uint32_t bh[4], bl[4];
                uint32_t boff = (uint32_t)((kg * 16 + (lane & 15)) * TS
                                           + ks * 16 + (lane >> 4) * 8) * 2;
                ldsm_x4(bh, kvb + boff);
                ldsm_x4(bl, kvb + 9216 + boff);
                mma16816(s[2 * kg],     qah[ks], bh[0], bh[2]);
                mma16816(s[2 * kg],     qah[ks], bl[0], bl[2]);
                mma16816(s[2 * kg],     qal[ks], bh[0], bh[2]);
                mma16816(s[2 * kg + 1], qah[ks], bh[1], bh[3]);
                mma16816(s[2 * kg + 1], qah[ks], bl[1], bl[3]);
                mma16816(s[2 * kg + 1], qal[ks], bh[1], bh[3]);
            }
        }

        // ---- masks (uniform branches; interior tiles: nothing)
        const int cq = 2 * (lane & 3);
        if (!allkm) {
            #pragma unroll
            for (int j = 0; j < 8; j++) {
                const uint32_t word = (j < 4) ? kb0 : kb1;
                #pragma unroll
                for (int e = 0; e < 4; e++) {
                    int bit = (8 * j + cq + (e & 1)) & 31;
                    if (!((word >> bit) & 1u)) s[j][e] = NEG_BIG2;
                }
            }
        }
        if (fullmask) {
            #pragma unroll
            for (int j = 0; j < 8; j++)
                #pragma unroll
                for (int e = 0; e < 4; e++) s[j][e] += MASK2;
        } else if (diag) {
            const int rbase = q0 + 16 * w + (lane >> 2);
            #pragma unroll
            for (int j = 0; j < 8; j++)
                #pragma unroll
                for (int e = 0; e < 4; e++) {
                    int row = rbase + ((e >> 1) << 3);
                    int col = k0 + 8 * j + cq + (e & 1);
                    if (row <= col) s[j][e] += MASK2;
                }
        }

        // ---- online softmax (log2 domain)
        float tmax0 = -INFINITY, tmax1 = -INFINITY;
        #pragma unroll
        for (int j = 0; j < 8; j++) {
            tmax0 = fmaxf(tmax0, fmaxf(s[j][0], s[j][1]));
            tmax1 = fmaxf(tmax1, fmaxf(s[j][2], s[j][3]));
        }
        tmax0 = fmaxf(tmax0, __shfl_xor_sync(0xffffffffu, tmax0, 1));
        tmax0 = fmaxf(tmax0, __shfl_xor_sync(0xffffffffu, tmax0, 2));
        tmax1 = fmaxf(tmax1, __shfl_xor_sync(0xffffffffu, tmax1, 1));
        tmax1 = fmaxf(tmax1, __shfl_xor_sync(0xffffffffu, tmax1, 2));

        float mn0 = fmaxf(m0, tmax0), mn1 = fmaxf(m1, tmax1);
        float a0 = exp2f_fast(m0 - mn0), a1 = exp2f_fast(m1 - mn1);
        m0 = mn0; m1 = mn1;

        float rs0 = 0.0f, rs1 = 0.0f;
        #pragma unroll
        for (int j = 0; j < 8; j++) {
            float p0 = exp2f_fast(s[j][0] - m0);
            float p1 = exp2f_fast(s[j][1] - m0);
            float p2 = exp2f_fast(s[j][2] - m1);
            float p3 = exp2f_fast(s[j][3] - m1);
            s[j][0] = p0; s[j][1] = p1; s[j][2] = p2; s[j][3] = p3;
            rs0 += p0 + p1; rs1 += p2 + p3;
        }
        rs0 += __shfl_xor_sync(0xffffffffu, rs0, 1);
        rs0 += __shfl_xor_sync(0xffffffffu, rs0, 2);
        rs1 += __shfl_xor_sync(0xffffffffu, rs1, 1);
        rs1 += __shfl_xor_sync(0xffffffffu, rs1, 2);
        l0 = l0 * a0 + rs0;
        l1 = l1 * a1 + rs1;

        #pragma unroll
        for (int j = 0; j < 8; j++) {
            O[j][0] *= a0; O[j][1] *= a0;
            O[j][2] *= a1; O[j][3] *= a1;
        }

        // ---- V ready?  (kt=0: V0 drained at top wait)
        if (kt > 0) {
            if (havePref) CP_WAIT(1); else CP_WAIT(0);
            __syncthreads();
        }

        // ---- O += P @ V
        #pragma unroll
        for (int ks = 0; ks < 4; ks++) {
            uint32_t pah[4], pal[4];
            bf16_split2(s[2 * ks][0],     s[2 * ks][1],     pah[0], pal[0]);
            bf16_split2(s[2 * ks][2],     s[2 * ks][3],     pah[1], pal[1]);
            bf16_split2(s[2 * ks + 1][0], s[2 * ks + 1][1], pah[2], pal[2]);
            bf16_split2(s[2 * ks + 1][2], s[2 * ks + 1][3], pah[3], pal[3]);
            #pragma unroll
            for (int dg = 0; dg < 4; dg++) {
                uint32_t vh[4], vl[4];
                uint32_t voff = (uint32_t)((ks * 16 + (lane & 15)) * TS
                                           + dg * 16 + (lane >> 4) * 8) * 2;
                ldsm_x4_t(vh, sb + AT_V + voff);
                ldsm_x4_t(vl, sb + AT_V + 9216 + voff);
                mma16816(O[2 * dg],     pah, vh[0], vh[1]);
                mma16816(O[2 * dg],     pah, vl[0], vl[1]);
                mma16816(O[2 * dg],     pal, vh[0], vh[1]);
                mma16816(O[2 * dg + 1], pah, vh[2], vh[3]);
                mma16816(O[2 * dg + 1], pah, vl[2], vl[3]);
                mma16816(O[2 * dg + 1], pal, vh[2], vh[3]);
            }
        }
    }

    // ---- epilogue (precomputed qf = qmask * rowmask)
    const int row0g = q0 + 16 * w + (lane >> 2);
    const int row1g = row0g + 8;
    const float f0 = (1.0f / l0) * g_qf[hb * T_ + row0g];
    const float f1 = (1.0f / l1) * g_qf[hb * T_ + row1g];
    #pragma unroll
    for (int j = 0; j < 8; j++) {
        int col = h * HD + 8 * j + 2 * (lane & 3);
        *(float2*)(out + (size_t)(b * T_ + row0g) * D_ + col) =
            make_float2(O[j][0] * f0, O[j][1] * f0);
        *(float2*)(out + (size_t)(b * T_ + row1g) * D_ + col) =
            make_float2(O[j][2] * f1, O[j][3] * f1);
    }
}

// ---------------------------------------------------------------------------
extern "C" void kernel_launch(void* const* d_in, const int* in_sizes, int n_in,
                              void* d_out, int out_size)
{
    const float* x    = (const float*)d_in[0];
    const int*   mask = (const int*)d_in[1];
    const float* Wq   = (const float*)d_in[2];
    const float* Wk   = (const float*)d_in[3];
    const float* Wv   = (const float*)d_in[4];
    float* out = (float*)d_out;

    cudaFuncSetAttribute(proj_tc_kernel,
                         cudaFuncAttributeMaxDynamicSharedMemorySize, PJ_SMEM);
    cudaFuncSetAttribute(attn_tc_kernel,
                         cudaFuncAttributeMaxDynamicSharedMemorySize, ATTN3_SMEM);

    split_inputs<<<1280, 256>>>(x, Wq, Wk, Wv);

    dim3 gproj(D_ / 64, MTOT / 128, 3);
    proj_tc_kernel<<<gproj, 256, PJ_SMEM>>>();

    mask_kernel<<<320, 256>>>(mask);

    dim3 gattn(T_ / 64, H_ * B_);
    attn_tc_kernel<<<gattn, 128, ATTN3_SMEM>>>(out);
}

// round 13
// speedup vs baseline: 1.0319x; 1.0319x over previous
#include <cuda_runtime.h>
#include <cuda_bf16.h>
#include <math.h>
#include <stdint.h>

#define B_   8
#define T_   1024
#define D_   640
#define H_   10
#define HD   64
#define MTOT (B_*T_)      // 8192
#define DW   (D_/2)       // 320 u32 per row (packed bf16x2)
#define WN   (640*320)    // u32 per weight plane
// log2-domain mask constants:  x * log2(e)
#define QSCALE   0.18033688011112042f   // 0.125 * log2(e)
#define MASK2    (-14426.950408889634f) // -10000 * log2(e)
#define NEG_BIG2 (-6.1963290e9f)        // (-2^32+1) * log2(e)

// pre-split inputs (written by split_inputs)
__device__ uint32_t g_Xh[MTOT * DW];
__device__ uint32_t g_Xl[MTOT * DW];
__device__ uint32_t g_Wh[3 * WN];
__device__ uint32_t g_Wl[3 * WN];
// Q/K/V packed bf16x2 hi/lo planes (Q pre-scaled by QSCALE)
__device__ uint32_t g_Qh[MTOT * DW];
__device__ uint32_t g_Ql[MTOT * DW];
__device__ uint32_t g_Kh[MTOT * DW];
__device__ uint32_t g_Kl[MTOT * DW];
__device__ uint32_t g_Vh[MTOT * DW];
__device__ uint32_t g_Vl[MTOT * DW];
// precomputed masks: km bit per (hb, t); qf = q-sign-mask * row-mask
__device__ uint32_t g_kmbits[H_ * B_ * (T_ / 32)];
__device__ float    g_qf[H_ * B_ * T_];

// ===========================================================================
__device__ __forceinline__ uint32_t smem_u32(const void* p) {
    uint32_t a;
    asm("{ .reg .u64 t; cvta.to.shared.u64 t, %1; cvt.u32.u64 %0, t; }"
        : "=r"(a) : "l"(p));
    return a;
}
__device__ __forceinline__ void ldsm_x4(uint32_t* r, uint32_t addr) {
    asm volatile("ldmatrix.sync.aligned.m8n8.x4.shared.b16 {%0,%1,%2,%3}, [%4];"
        : "=r"(r[0]), "=r"(r[1]), "=r"(r[2]), "=r"(r[3]) : "r"(addr));
}
__device__ __forceinline__ void ldsm_x4_t(uint32_t* r, uint32_t addr) {
    asm volatile("ldmatrix.sync.aligned.m8n8.x4.trans.shared.b16 {%0,%1,%2,%3}, [%4];"
        : "=r"(r[0]), "=r"(r[1]), "=r"(r[2]), "=r"(r[3]) : "r"(addr));
}
__device__ __forceinline__ void mma16816(float* c, const uint32_t* a,
                                         uint32_t b0, uint32_t b1) {
    asm volatile(
        "mma.sync.aligned.m16n8k16.row.col.f32.bf16.bf16.f32 "
        "{%0,%1,%2,%3}, {%4,%5,%6,%7}, {%8,%9}, {%0,%1,%2,%3};"
        : "+f"(c[0]), "+f"(c[1]), "+f"(c[2]), "+f"(c[3])
        : "r"(a[0]), "r"(a[1]), "r"(a[2]), "r"(a[3]), "r"(b0), "r"(b1));
}
__device__ __forceinline__ float exp2f_fast(float x) {
    float r; asm("ex2.approx.f32 %0, %1;" : "=f"(r) : "f"(x)); return r;
}
// split pair (a,b) -> bf16 hi/lo packed bf16x2 (a low half)
__device__ __forceinline__ void bf16_split2(float a, float b,
                                            uint32_t& hi, uint32_t& lo) {
    asm("cvt.rn.bf16x2.f32 %0, %1, %2;" : "=r"(hi) : "f"(b), "f"(a));
    float ar = a - __uint_as_float(hi << 16);
    float br = b - __uint_as_float(hi & 0xFFFF0000u);
    asm("cvt.rn.bf16x2.f32 %0, %1, %2;" : "=r"(lo) : "f"(br), "f"(ar));
}
__device__ __forceinline__ void cp16(uint32_t dst, const void* src) {
    asm volatile("cp.async.cg.shared.global [%0], [%1], 16;"
        :: "r"(dst), "l"(src));
}
#define CP_COMMIT() asm volatile("cp.async.commit_group;" ::: "memory")
#define CP_WAIT(n)  asm volatile("cp.async.wait_group %0;" :: "n"(n) : "memory")

// ===========================================================================
// split_inputs: x and Wq/Wk/Wv fp32 -> packed bf16x2 hi/lo planes.
// ===========================================================================
__global__ void __launch_bounds__(256) split_inputs(
        const float* __restrict__ x,  const float* __restrict__ Wq,
        const float* __restrict__ Wk, const float* __restrict__ Wv)
{
    const int NX = MTOT * DW;
    const int NTOT = NX + 3 * WN;
    for (int i = blockIdx.x * 256 + threadIdx.x; i < NTOT;
         i += gridDim.x * 256) {
        if (i < NX) {
            float2 v = ((const float2*)x)[i];
            bf16_split2(v.x, v.y, g_Xh[i], g_Xl[i]);
        } else {
            int j = i - NX;
            int w = j / WN, r = j - w * WN;
            const float2* src = (const float2*)(w == 0 ? Wq : w == 1 ? Wk : Wv);
            float2 v = src[r];
            bf16_split2(v.x, v.y, g_Wh[j], g_Wl[j]);
        }
    }
}

// ===========================================================================
// Projection: double-buffered cp.async GEMM on pre-split bf16 planes.
// Q output (z==0) pre-scaled by QSCALE.  Epilogue also produces the key
// sign-bits (z==1 -> g_kmbits) and query factor (z==0 -> g_qf) for free:
// each N-block is exactly one head, so masks are CTA-local reductions.
// ===========================================================================
#define PS_AHI 0
#define PS_ALO 18432
#define PS_BHI 36864
#define PS_BLO 46080
#define PJ_STAGE 55296
#define PJ_SMEM  (2 * PJ_STAGE)   // 110592

__global__ void __launch_bounds__(256, 2) proj_tc_kernel(
        const int* __restrict__ mask)
{
    const int z = blockIdx.z;
    uint32_t* outh = (z == 0) ? g_Qh : (z == 1) ? g_Kh : g_Vh;
    uint32_t* outl = (z == 0) ? g_Ql : (z == 1) ? g_Kl : g_Vl;
    const uint32_t* wh = g_Wh + z * WN;
    const uint32_t* wl = g_Wl + z * WN;
    const float sc = (z == 0) ? QSCALE : 1.0f;

    extern __shared__ char smem[];
    const uint32_t sb = smem_u32(smem);

    const int tid  = threadIdx.x;
    const int lane = tid & 31;
    const int wid  = tid >> 5;
    const int wm   = (wid & 3) * 32;
    const int wn   = (wid >> 2) * 32;
    const int row0 = blockIdx.y * 128;
    const int col0 = blockIdx.x * 64;
    const int colw = col0 >> 1;

    auto load_chunk = [&](int s, int c) {
        const uint32_t base = sb + s * PJ_STAGE;
        const int kw = c * 32;
        #pragma unroll
        for (int i = 0; i < 8; i++) {
            const int plane = i >> 2;
            int rem = (tid + i * 256) & 1023;
            int r = rem >> 3, seg = rem & 7;
            const uint32_t* src = (plane ? g_Xl : g_Xh)
                                  + (size_t)(row0 + r) * DW + kw + seg * 4;
            cp16(base + (plane ? PS_ALO : PS_AHI) + r * 144 + seg * 16, src);
        }
        #pragma unroll
        for (int i = 0; i < 4; i++) {
            const int plane = i >> 1;
            int rem = (tid + i * 256) & 511;
            int kk = rem >> 3, seg = rem & 7;
            const uint32_t* src = (plane ? wl : wh)
                                  + (size_t)(c * 64 + kk) * 320 + colw + seg * 4;
            cp16(base + (plane ? PS_BLO : PS_BHI) + kk * 144 + seg * 16, src);
        }
        CP_COMMIT();
    };

    float acc[2][4][4] = {};
    load_chunk(0, 0);

    for (int c = 0; c < 10; c++) {
        if (c < 9) { load_chunk((c + 1) & 1, c + 1); CP_WAIT(1); }
        else       { CP_WAIT(0); }
        __syncthreads();

        const uint32_t base = sb + (c & 1) * PJ_STAGE;
        #pragma unroll
        for (int ks = 0; ks < 4; ks++) {
            const int k = ks * 16;
            uint32_t ah[2][4], al[2][4];
            #pragma unroll
            for (int mi = 0; mi < 2; mi++) {
                uint32_t off = (uint32_t)((wm + mi * 16 + (lane & 15)) * 72
                                          + k + (lane >> 4) * 8) * 2;
                ldsm_x4(ah[mi], base + PS_AHI + off);
                ldsm_x4(al[mi], base + PS_ALO + off);
            }
            uint32_t bh[2][4], bl[2][4];
            #pragma unroll
            for (int nj = 0; nj < 2; nj++) {
                uint32_t off = (uint32_t)((k + (lane & 15)) * 72
                                          + wn + nj * 16 + (lane >> 4) * 8) * 2;
                ldsm_x4_t(bh[nj], base + PS_BHI + off);
                ldsm_x4_t(bl[nj], base + PS_BLO + off);
            }
            #pragma unroll
            for (int mi = 0; mi < 2; mi++)
                #pragma unroll
                for (int ni = 0; ni < 4; ni++) {
                    int nj = ni >> 1, hf = (ni & 1) * 2;
                    mma16816(acc[mi][ni], ah[mi], bh[nj][hf], bh[nj][hf + 1]);
                    mma16816(acc[mi][ni], ah[mi], bl[nj][hf], bl[nj][hf + 1]);
                    mma16816(acc[mi][ni], al[mi], bh[nj][hf], bh[nj][hf + 1]);
                }
        }
        __syncthreads();
    }

    // ---- store epilogue
    const int gid = lane >> 2, t2 = lane & 3;
    #pragma unroll
    for (int mi = 0; mi < 2; mi++) {
        #pragma unroll
        for (int ni = 0; ni < 4; ni++) {
            int r0r = row0 + wm + mi * 16 + gid;
            int cc  = col0 + wn + ni * 8 + t2 * 2;
            uint32_t h0, l0, h1, l1;
            bf16_split2(acc[mi][ni][0] * sc, acc[mi][ni][1] * sc, h0, l0);
            bf16_split2(acc[mi][ni][2] * sc, acc[mi][ni][3] * sc, h1, l1);
            size_t i0 = (size_t)r0r * DW + (cc >> 1);
            size_t i1 = (size_t)(r0r + 8) * DW + (cc >> 1);
            outh[i0] = h0; outl[i0] = l0;
            outh[i1] = h1; outl[i1] = l1;
        }
    }

    // ---- mask epilogue (z==0: g_qf, z==1: g_kmbits), free from registers
    if (z < 2) {
        // per-thread nonzero flags for its 4 distinct rows
        uint32_t nz[4] = {0, 0, 0, 0};
        #pragma unroll
        for (int mi = 0; mi < 2; mi++)
            #pragma unroll
            for (int ni = 0; ni < 4; ni++) {
                nz[mi * 2 + 0] |= __float_as_uint(acc[mi][ni][0])
                                | __float_as_uint(acc[mi][ni][1]);
                nz[mi * 2 + 1] |= __float_as_uint(acc[mi][ni][2])
                                | __float_as_uint(acc[mi][ni][3]);
            }
        uint32_t pack = ((nz[0] & 0x7FFFFFFFu) ? 1u : 0u)
                      | ((nz[1] & 0x7FFFFFFFu) ? 2u : 0u)
                      | ((nz[2] & 0x7FFFFFFFu) ? 4u : 0u)
                      | ((nz[3] & 0x7FFFFFFFu) ? 8u : 0u);
        pack |= __shfl_xor_sync(0xffffffffu, pack, 1);
        pack |= __shfl_xor_sync(0xffffffffu, pack, 2);   // OR over warp's 32 cols

        uint32_t* flags = (uint32_t*)smem;   // reuse stage 0 (drained)
        if (tid < 128) flags[tid] = 0;
        __syncthreads();
        if (wid < 4 && t2 == 0) {
            flags[wm + 0  + gid] = pack & 1u;
            flags[wm + 8  + gid] = pack & 2u;
            flags[wm + 16 + gid] = pack & 4u;
            flags[wm + 24 + gid] = pack & 8u;
        }
        __syncthreads();
        if (wid >= 4 && t2 == 0) {
            flags[wm + 0  + gid] |= pack & 1u;
            flags[wm + 8  + gid] |= pack & 2u;
            flags[wm + 16 + gid] |= pack & 4u;
            flags[wm + 24 + gid] |= pack & 8u;
        }
        __syncthreads();

        const int h  = col0 >> 6;
        const int b  = row0 >> 10;
        const int hb = h * 8 + b;
        const int tbase = row0 & 1023;
        if (tid < 128) {
            uint32_t f = flags[tid];
            if (z == 1) {
                uint32_t word = __ballot_sync(0xffffffffu, f != 0);
                if (lane == 0)
                    g_kmbits[hb * 32 + (tbase >> 5) + (tid >> 5)] = word;
            } else {
                int t = tbase + tid;
                g_qf[hb * T_ + t] = (f ? 1.0f : 0.0f) * (float)mask[b * T_ + t];
            }
        }
    }
}

// ===========================================================================
// Tensor-core flash attention.  CTA = (64-q-tile, head, batch), 4 warps.
// Heaviest q-tiles scheduled first (qt = 0, 15, 14, ..., 1).
// ===========================================================================
#define TS 72
#define AT_QHI 0
#define AT_QLO 9216
#define AT_K0  18432          // 2 stages x (KHI 9216 + KLO 9216)
#define AT_V   55296          // VHI + VLO
#define ATTN3_SMEM 73728

__global__ void __launch_bounds__(128, 3) attn_tc_kernel(float* __restrict__ out)
{
    const int qt = (blockIdx.x == 0) ? 0 : (16 - blockIdx.x);  // heavy first
    const int q0 = qt * 64;
    const int hb = blockIdx.y;
    const int b  = hb & 7;
    const int h  = hb >> 3;

    extern __shared__ char sm[];
    const uint32_t sb = smem_u32(sm);

    const int tid  = threadIdx.x;
    const int lane = tid & 31;
    const int w    = tid >> 5;

    const size_t kvrow = (size_t)(b * T_) * DW + h * 32;

    // ---- Q tile
    {
        const uint32_t* qh = g_Qh + (size_t)(b * T_ + q0) * DW + h * 32;
        const uint32_t* ql = g_Ql + (size_t)(b * T_ + q0) * DW + h * 32;
        #pragma unroll
        for (int i = 0; i < 8; i++) {
            const int plane = i >> 2;
            int rem = (tid + i * 128) & 511;
            int r = rem >> 3, seg = rem & 7;
            cp16(sb + (plane ? AT_QLO : AT_QHI) + r * 144 + seg * 16,
                 (plane ? ql : qh) + (size_t)r * DW + seg * 4);
        }
        CP_COMMIT(); CP_WAIT(0);
    }
    __syncthreads();

    uint32_t qah[4][4], qal[4][4];
    #pragma unroll
    for (int ks = 0; ks < 4; ks++) {
        uint32_t aoff = (uint32_t)((16 * w + (lane & 15)) * TS
                                   + ks * 16 + (lane >> 4) * 8) * 2;
        ldsm_x4(qah[ks], sb + AT_QHI + aoff);
        ldsm_x4(qal[ks], sb + AT_QLO + aoff);
    }

    const int nkt = (q0 == 0) ? (T_ / 64) : (qt + 1);

    auto commitK = [&](int stg, int kt2) {
        const size_t gbase = kvrow + (size_t)(kt2 * 64) * DW;
        const uint32_t* kh = g_Kh + gbase;
        const uint32_t* kl = g_Kl + gbase;
        const uint32_t kbase = sb + AT_K0 + stg * 18432;
        #pragma unroll
        for (int i = 0; i < 8; i++) {
            const int plane = i >> 2;
            int rem = (tid + i * 128) & 511;
            int r = rem >> 3, seg = rem & 7;
            cp16(kbase + plane * 9216 + r * 144 + seg * 16,
                 (plane ? kl : kh) + (size_t)r * DW + seg * 4);
        }
        CP_COMMIT();
    };
    auto commitV = [&](int kt2) {
        const size_t gbase = kvrow + (size_t)(kt2 * 64) * DW;
        const uint32_t* vh = g_Vh + gbase;
        const uint32_t* vl = g_Vl + gbase;
        #pragma unroll
        for (int i = 0; i < 8; i++) {
            const int plane = i >> 2;
            int rem = (tid + i * 128) & 511;
            int r = rem >> 3, seg = rem & 7;
            cp16(sb + AT_V + plane * 9216 + r * 144 + seg * 16,
                 (plane ? vl : vh) + (size_t)r * DW + seg * 4);
        }
        CP_COMMIT();
    };

    commitK(0, 0);
    commitV(0);

    float m0 = -INFINITY, m1 = -INFINITY, l0 = 0.0f, l1 = 0.0f;
    float O[8][4] = {};

    for (int kt = 0; kt < nkt; kt++) {
        const int k0 = kt * 64;
        const bool fullmask = kt > qt;       // only q-tile 0
        const bool diag = (kt == qt);
        const uint32_t kvb = sb + AT_K0 + (kt & 1) * 18432;

        CP_WAIT(0);                 // K_kt resident (kt=0: V0 too)
        __syncthreads();            // all prior readers done

        if (kt > 0) commitV(kt);                       // V buf free now
        const bool havePref = (kt + 1 < nkt);
        if (havePref) commitK((kt + 1) & 1, kt + 1);   // other stage free

        // km bits for this tile (uniform load, L1-broadcast)
        const uint32_t kb0 = g_kmbits[hb * 32 + (k0 >> 5)];
        const uint32_t kb1 = g_kmbits[hb * 32 + (k0 >> 5) + 1];
        const bool allkm = (kb0 & kb1) == 0xFFFFFFFFu;

        // ---- S = Q K^T (3-term bf16 split); log2-domain scores
        float s[8][4] = {};
        #pragma unroll
        for (int ks = 0; ks < 4; ks++) {
            #pragma unroll
            for (int kg = 0; kg < 4; kg++) {
                uint32_t bh[4], bl[4];
                uint32_t boff = (uint32_t)((kg * 16 + (lane & 15)) * TS
                                           + ks * 16 + (lane >> 4) * 8) * 2;
                ldsm_x4(bh, kvb + boff);
                ldsm_x4(bl, kvb + 9216 + boff);
                mma16816(s[2 * kg],     qah[ks], bh[0], bh[2]);
                mma16816(s[2 * kg],     qah[ks], bl[0], bl[2]);
                mma16816(s[2 * kg],     qal[ks], bh[0], bh[2]);
                mma16816(s[2 * kg + 1], qah[ks], bh[1], bh[3]);
                mma16816(s[2 * kg + 1], qah[ks], bl[1], bl[3]);
                mma16816(s[2 * kg + 1], qal[ks], bh[1], bh[3]);
            }
        }

        // ---- masks (uniform branches; interior tiles: nothing)
        const int cq = 2 * (lane & 3);
        if (!allkm) {
            #pragma unroll
            for (int j = 0; j < 8; j++) {
                const uint32_t word = (j < 4) ? kb0 : kb1;
                #pragma unroll
                for (int e = 0; e < 4; e++) {
                    int bit = (8 * j + cq + (e & 1)) & 31;
                    if (!((word >> bit) & 1u)) s[j][e] = NEG_BIG2;
                }
            }
        }
        if (fullmask) {
            #pragma unroll
            for (int j = 0; j < 8; j++)
                #pragma unroll
                for (int e = 0; e < 4; e++) s[j][e] += MASK2;
        } else if (diag) {
            const int rbase = q0 + 16 * w + (lane >> 2);
            #pragma unroll
            for (int j = 0; j < 8; j++)
                #pragma unroll
                for (int e = 0; e < 4; e++) {
                    int row = rbase + ((e >> 1) << 3);
                    int col = k0 + 8 * j + cq + (e & 1);
                    if (row <= col) s[j][e] += MASK2;
                }
        }

        // ---- online softmax (log2 domain)
        float tmax0 = -INFINITY, tmax1 = -INFINITY;
        #pragma unroll
        for (int j = 0; j < 8; j++) {
            tmax0 = fmaxf(tmax0, fmaxf(s[j][0], s[j][1]));
            tmax1 = fmaxf(tmax1, fmaxf(s[j][2], s[j][3]));
        }
        tmax0 = fmaxf(tmax0, __shfl_xor_sync(0xffffffffu, tmax0, 1));
        tmax0 = fmaxf(tmax0, __shfl_xor_sync(0xffffffffu, tmax0, 2));
        tmax1 = fmaxf(tmax1, __shfl_xor_sync(0xffffffffu, tmax1, 1));
        tmax1 = fmaxf(tmax1, __shfl_xor_sync(0xffffffffu, tmax1, 2));

        float mn0 = fmaxf(m0, tmax0), mn1 = fmaxf(m1, tmax1);
        float a0 = exp2f_fast(m0 - mn0), a1 = exp2f_fast(m1 - mn1);
        m0 = mn0; m1 = mn1;

        float rs0 = 0.0f, rs1 = 0.0f;
        #pragma unroll
        for (int j = 0; j < 8; j++) {
            float p0 = exp2f_fast(s[j][0] - m0);
            float p1 = exp2f_fast(s[j][1] - m0);
            float p2 = exp2f_fast(s[j][2] - m1);
            float p3 = exp2f_fast(s[j][3] - m1);
            s[j][0] = p0; s[j][1] = p1; s[j][2] = p2; s[j][3] = p3;
            rs0 += p0 + p1; rs1 += p2 + p3;
        }
        rs0 += __shfl_xor_sync(0xffffffffu, rs0, 1);
        rs0 += __shfl_xor_sync(0xffffffffu, rs0, 2);
        rs1 += __shfl_xor_sync(0xffffffffu, rs1, 1);
        rs1 += __shfl_xor_sync(0xffffffffu, rs1, 2);
        l0 = l0 * a0 + rs0;
        l1 = l1 * a1 + rs1;

        #pragma unroll
        for (int j = 0; j < 8; j++) {
            O[j][0] *= a0; O[j][1] *= a0;
            O[j][2] *= a1; O[j][3] *= a1;
        }

        // ---- V ready?  (kt=0: V0 drained at top wait)
        if (kt > 0) {
            if (havePref) CP_WAIT(1); else CP_WAIT(0);
            __syncthreads();
        }

        // ---- O += P @ V
        #pragma unroll
        for (int ks = 0; ks < 4; ks++) {
            uint32_t pah[4], pal[4];
            bf16_split2(s[2 * ks][0],     s[2 * ks][1],     pah[0], pal[0]);
            bf16_split2(s[2 * ks][2],     s[2 * ks][3],     pah[1], pal[1]);
            bf16_split2(s[2 * ks + 1][0], s[2 * ks + 1][1], pah[2], pal[2]);
            bf16_split2(s[2 * ks + 1][2], s[2 * ks + 1][3], pah[3], pal[3]);
            #pragma unroll
            for (int dg = 0; dg < 4; dg++) {
                uint32_t vh[4], vl[4];
                uint32_t voff = (uint32_t)((ks * 16 + (lane & 15)) * TS
                                           + dg * 16 + (lane >> 4) * 8) * 2;
                ldsm_x4_t(vh, sb + AT_V + voff);
                ldsm_x4_t(vl, sb + AT_V + 9216 + voff);
                mma16816(O[2 * dg],     pah, vh[0], vh[1]);
                mma16816(O[2 * dg],     pah, vl[0], vl[1]);
                mma16816(O[2 * dg],     pal, vh[0], vh[1]);
                mma16816(O[2 * dg + 1], pah, vh[2], vh[3]);
                mma16816(O[2 * dg + 1], pah, vl[2], vl[3]);
                mma16816(O[2 * dg + 1], pal, vh[2], vh[3]);
            }
        }
    }

    // ---- epilogue (precomputed qf = qmask * rowmask)
    const int row0g = q0 + 16 * w + (lane >> 2);
    const int row1g = row0g + 8;
    const float f0 = (1.0f / l0) * g_qf[hb * T_ + row0g];
    const float f1 = (1.0f / l1) * g_qf[hb * T_ + row1g];
    #pragma unroll
    for (int j = 0; j < 8; j++) {
        int col = h * HD + 8 * j + 2 * (lane & 3);
        *(float2*)(out + (size_t)(b * T_ + row0g) * D_ + col) =
            make_float2(O[j][0] * f0, O[j][1] * f0);
        *(float2*)(out + (size_t)(b * T_ + row1g) * D_ + col) =
            make_float2(O[j][2] * f1, O[j][3] * f1);
    }
}

// ---------------------------------------------------------------------------
extern "C" void kernel_launch(void* const* d_in, const int* in_sizes, int n_in,
                              void* d_out, int out_size)
{
    const float* x    = (const float*)d_in[0];
    const int*   mask = (const int*)d_in[1];
    const float* Wq   = (const float*)d_in[2];
    const float* Wk   = (const float*)d_in[3];
    const float* Wv   = (const float*)d_in[4];
    float* out = (float*)d_out;

    cudaFuncSetAttribute(proj_tc_kernel,
                         cudaFuncAttributeMaxDynamicSharedMemorySize, PJ_SMEM);
    cudaFuncSetAttribute(attn_tc_kernel,
                         cudaFuncAttributeMaxDynamicSharedMemorySize, ATTN3_SMEM);

    split_inputs<<<1280, 256>>>(x, Wq, Wk, Wv);

    dim3 gproj(D_ / 64, MTOT / 128, 3);
    proj_tc_kernel<<<gproj, 256, PJ_SMEM>>>(mask);

    dim3 gattn(T_ / 64, H_ * B_);
    attn_tc_kernel<<<gattn, 128, ATTN3_SMEM>>>(out);
}